// round 2
// baseline (speedup 1.0000x reference)
#include <cuda_runtime.h>
#include <math.h>

// ---------------- problem constants ----------------
#define NN      65536      // nodes (conformer graph)
#define NT      8192       // topo nodes
#define ECONF   1048576
#define EGRAPH  32768
#define NMOL    256
#define HD      128
#define FD      64
#define GD      50

#define GSTEP   0.20408163265306123f   // 10/49
#define GC      (-12.005f)             // -0.5/(10/49)^2
#define PI10    0.31415926535897931f

// ---------------- scratch (__device__ globals; no cudaMalloc) ----------------
__device__ float g_ew[ECONF];
__device__ float g_cwin[ECONF];
__device__ float g_x[NN * HD];
__device__ float g_h[NN * FD];
__device__ float g_agg[NN * FD];
__device__ float g_t1[NN * HD];
__device__ float g_t2[NN * HD];
__device__ float g_xagg[NT * HD];
__device__ float g_magg[NT * HD];
__device__ float g_hg0[NT * HD];
__device__ float g_hg1[NT * HD];
__device__ float g_hg2[NT * HD];
__device__ float g_hg3[NT * HD];
__device__ float g_hgf[NT * HD];
__device__ float g_pool[NMOL * HD];

// ---------------- edge precompute: distance + cosine window ----------------
__global__ void __launch_bounds__(256) eprep_kernel(const int* __restrict__ eic,
                                                    const float* __restrict__ pos) {
    int e = blockIdx.x * 256 + threadIdx.x;
    int r = eic[e], c = eic[ECONF + e];
    float dx = pos[r * 3 + 0] - pos[c * 3 + 0];
    float dy = pos[r * 3 + 1] - pos[c * 3 + 1];
    float dz = pos[r * 3 + 2] - pos[c * 3 + 2];
    float w = sqrtf(dx * dx + dy * dy + dz * dz + 1e-12f);
    g_ew[e] = w;
    g_cwin[e] = 0.5f * (cosf(w * PI10) + 1.0f);
}

// ---------------- x0 = atom_emb[x_topo][cnb] (cnb structural) ----------------
__global__ void __launch_bounds__(256) initx_kernel(const int* __restrict__ xt,
                                                    const float* __restrict__ aemb) {
    int idx = blockIdx.x * 256 + threadIdx.x;
    int n = idx >> 7, f = idx & 127;
    int s = ((n >> 8) << 5) | (n & 31);
    g_x[idx] = aemb[xt[s] * HD + f];
}

// ---------------- zero kernels ----------------
__global__ void __launch_bounds__(256) zero_agg_kernel() {
    int i = blockIdx.x * 256 + threadIdx.x;
    *(float4*)&g_agg[i << 2] = make_float4(0.f, 0.f, 0.f, 0.f);
}
__global__ void __launch_bounds__(256) zero_magg_kernel() {
    int i = blockIdx.x * 256 + threadIdx.x;
    *(float4*)&g_magg[i << 2] = make_float4(0.f, 0.f, 0.f, 0.f);
}

// ---------------- generic tiled fp32 GEMM: C[M,BN] = A[M,K] @ B[K,BN] ----------------
// SEL chooses (A, C) among device globals. mode: 0 none, 1 +bias, 2 +bias+relu.
template <int BN, int SEL>
__global__ void __launch_bounds__(256) gemm_kernel(const float* __restrict__ B,
                                                   const float* __restrict__ bias,
                                                   int K, int mode) {
    const float* A;
    float* C;
    if constexpr (SEL == 0) { A = g_x;   C = g_h;  }
    else if constexpr (SEL == 1) { A = g_agg; C = g_t1; }
    else if constexpr (SEL == 2) { A = g_t1;  C = g_t2; }
    else if constexpr (SEL == 3) { A = g_hg0; C = g_hg1; }
    else                         { A = g_hg2; C = g_hg3; }

    __shared__ float As[64 * 36];
    __shared__ float Bs[32 * BN];
    const int t = threadIdx.x;
    const int m0 = blockIdx.x * 64;
    const int tr = t >> 4, tc = t & 15;
    constexpr int NC = BN / 16;
    float acc[4][NC];
#pragma unroll
    for (int i = 0; i < 4; i++)
#pragma unroll
        for (int j = 0; j < NC; j++) acc[i][j] = 0.f;

    for (int k0 = 0; k0 < K; k0 += 32) {
        __syncthreads();
#pragma unroll
        for (int q = 0; q < 2; q++) {
            int p = t + (q << 8);
            int r = p >> 3, kq = (p & 7) << 2;
            float4 v = *(const float4*)&A[(m0 + r) * K + k0 + kq];
            *(float4*)&As[r * 36 + kq] = v;
        }
#pragma unroll
        for (int q = 0; q < BN / 32; q++) {
            int p = t + (q << 8);
            int kk = p / (BN / 4), cc = (p % (BN / 4)) << 2;
            *(float4*)&Bs[kk * BN + cc] = *(const float4*)&B[(k0 + kk) * BN + cc];
        }
        __syncthreads();
#pragma unroll 8
        for (int kk = 0; kk < 32; kk++) {
            float a[4];
#pragma unroll
            for (int i = 0; i < 4; i++) a[i] = As[(tr * 4 + i) * 36 + kk];
            float4 b0 = *(const float4*)&Bs[kk * BN + (tc << 2)];
#pragma unroll
            for (int i = 0; i < 4; i++) {
                acc[i][0] = fmaf(a[i], b0.x, acc[i][0]);
                acc[i][1] = fmaf(a[i], b0.y, acc[i][1]);
                acc[i][2] = fmaf(a[i], b0.z, acc[i][2]);
                acc[i][3] = fmaf(a[i], b0.w, acc[i][3]);
            }
            if constexpr (BN == 128) {
                float4 b1 = *(const float4*)&Bs[kk * BN + 64 + (tc << 2)];
#pragma unroll
                for (int i = 0; i < 4; i++) {
                    acc[i][4] = fmaf(a[i], b1.x, acc[i][4]);
                    acc[i][5] = fmaf(a[i], b1.y, acc[i][5]);
                    acc[i][6] = fmaf(a[i], b1.z, acc[i][6]);
                    acc[i][7] = fmaf(a[i], b1.w, acc[i][7]);
                }
            }
        }
    }
    float4 bb0 = make_float4(0.f, 0.f, 0.f, 0.f), bb1 = make_float4(0.f, 0.f, 0.f, 0.f);
    if (mode != 0) {
        bb0 = *(const float4*)&bias[tc << 2];
        if constexpr (BN == 128) bb1 = *(const float4*)&bias[64 + (tc << 2)];
    }
#pragma unroll
    for (int i = 0; i < 4; i++) {
        int r = m0 + tr * 4 + i;
        float4 o0 = make_float4(acc[i][0] + bb0.x, acc[i][1] + bb0.y,
                                acc[i][2] + bb0.z, acc[i][3] + bb0.w);
        if (mode == 2) {
            o0.x = fmaxf(o0.x, 0.f); o0.y = fmaxf(o0.y, 0.f);
            o0.z = fmaxf(o0.z, 0.f); o0.w = fmaxf(o0.w, 0.f);
        }
        *(float4*)&C[r * BN + (tc << 2)] = o0;
        if constexpr (BN == 128) {
            float4 o1 = make_float4(acc[i][4] + bb1.x, acc[i][5] + bb1.y,
                                    acc[i][6] + bb1.z, acc[i][7] + bb1.w);
            if (mode == 2) {
                o1.x = fmaxf(o1.x, 0.f); o1.y = fmaxf(o1.y, 0.f);
                o1.z = fmaxf(o1.z, 0.f); o1.w = fmaxf(o1.w, 0.f);
            }
            *(float4*)&C[r * BN + 64 + (tc << 2)] = o1;
        }
    }
}

// ---------------- fused CFConv edge kernel ----------------
// CTA = 256 threads / 128 edges. gauss -> relu(g@W1+b1) -> (u@W2+b2)*cwin
// -> gather h[row], scatter-atomic into agg[col].
#define SM_W1  0
#define SM_W2  3200
#define SM_EA  7296
#define SM_U   13696       // 64 rows x 132 (padded)
#define SM_B1  22144
#define SM_B2  22208
#define SM_EW  22272
#define SM_CW  22400
#define SM_RC  22528       // int row[128], col[128]
#define EDGE_SMEM_FLOATS 22784
#define EDGE_SMEM_BYTES  (EDGE_SMEM_FLOATS * 4)

__global__ void __launch_bounds__(256) edge_kernel(const float* __restrict__ W1,
                                                   const float* __restrict__ B1,
                                                   const float* __restrict__ W2,
                                                   const float* __restrict__ B2,
                                                   const int* __restrict__ eic) {
    extern __shared__ float sm[];
    float* sW1 = sm + SM_W1;
    float* sW2 = sm + SM_W2;
    float* sEA = sm + SM_EA;
    float* sU  = sm + SM_U;
    float* sB1 = sm + SM_B1;
    float* sB2 = sm + SM_B2;
    float* sEW = sm + SM_EW;
    float* sCW = sm + SM_CW;
    int*   sRC = (int*)(sm + SM_RC);

    const int t = threadIdx.x;
    const int e0 = blockIdx.x * 128;
#pragma unroll 4
    for (int i = t; i < 3200; i += 256) sW1[i] = W1[i];
#pragma unroll 4
    for (int i = t; i < 4096; i += 256) sW2[i] = W2[i];
    if (t < 64) { sB1[t] = B1[t]; sB2[t] = B2[t]; }
    if (t < 128) {
        sRC[t]       = eic[e0 + t];
        sRC[128 + t] = eic[ECONF + e0 + t];
        sEW[t] = g_ew[e0 + t];
        sCW[t] = g_cwin[e0 + t];
    }
    __syncthreads();

    // gaussians: sEA[k][e]
#pragma unroll 1
    for (int i = t; i < GD * 128; i += 256) {
        int k = i >> 7, e = i & 127;
        float d = sEW[e] - (float)k * GSTEP;
        sEA[i] = expf(GC * d * d);
    }
    __syncthreads();

    const int tf = t & 15, te = t >> 4;

    // GEMM1: u[e][f] = relu(b1[f] + sum_k ea[e][k] * W1[k][f])
    {
        float acc[8][4];
#pragma unroll
        for (int i = 0; i < 8; i++)
#pragma unroll
            for (int j = 0; j < 4; j++) acc[i][j] = sB1[(tf << 2) + j];
#pragma unroll 5
        for (int k = 0; k < GD; k++) {
            float4 b = *(const float4*)&sW1[k * 64 + (tf << 2)];
            float4 a0 = *(const float4*)&sEA[(k << 7) + (te << 3)];
            float4 a1 = *(const float4*)&sEA[(k << 7) + (te << 3) + 4];
            float av[8] = {a0.x, a0.y, a0.z, a0.w, a1.x, a1.y, a1.z, a1.w};
#pragma unroll
            for (int i = 0; i < 8; i++) {
                acc[i][0] = fmaf(av[i], b.x, acc[i][0]);
                acc[i][1] = fmaf(av[i], b.y, acc[i][1]);
                acc[i][2] = fmaf(av[i], b.z, acc[i][2]);
                acc[i][3] = fmaf(av[i], b.w, acc[i][3]);
            }
        }
#pragma unroll
        for (int j = 0; j < 4; j++) {
            float4 v0 = make_float4(fmaxf(acc[0][j], 0.f), fmaxf(acc[1][j], 0.f),
                                    fmaxf(acc[2][j], 0.f), fmaxf(acc[3][j], 0.f));
            float4 v1 = make_float4(fmaxf(acc[4][j], 0.f), fmaxf(acc[5][j], 0.f),
                                    fmaxf(acc[6][j], 0.f), fmaxf(acc[7][j], 0.f));
            *(float4*)&sU[((tf << 2) + j) * 132 + (te << 3)] = v0;
            *(float4*)&sU[((tf << 2) + j) * 132 + (te << 3) + 4] = v1;
        }
    }
    __syncthreads();

    // GEMM2: wf[e][f] = (b2[f] + sum_k u[e][k]*W2[k][f]) * cwin[e]; then scatter
    {
        float acc[8][4];
#pragma unroll
        for (int i = 0; i < 8; i++)
#pragma unroll
            for (int j = 0; j < 4; j++) acc[i][j] = sB2[(tf << 2) + j];
#pragma unroll 4
        for (int k = 0; k < 64; k++) {
            float4 b = *(const float4*)&sW2[k * 64 + (tf << 2)];
            float4 a0 = *(const float4*)&sU[k * 132 + (te << 3)];
            float4 a1 = *(const float4*)&sU[k * 132 + (te << 3) + 4];
            float av[8] = {a0.x, a0.y, a0.z, a0.w, a1.x, a1.y, a1.z, a1.w};
#pragma unroll
            for (int i = 0; i < 8; i++) {
                acc[i][0] = fmaf(av[i], b.x, acc[i][0]);
                acc[i][1] = fmaf(av[i], b.y, acc[i][1]);
                acc[i][2] = fmaf(av[i], b.z, acc[i][2]);
                acc[i][3] = fmaf(av[i], b.w, acc[i][3]);
            }
        }
#pragma unroll
        for (int i = 0; i < 8; i++) {
            int e = (te << 3) + i;
            float cw = sCW[e];
            int r = sRC[e], c = sRC[128 + e];
            float4 hv = *(const float4*)&g_h[r * 64 + (tf << 2)];
            int base = c * 64 + (tf << 2);
            atomicAdd(&g_agg[base + 0], acc[i][0] * cw * hv.x);
            atomicAdd(&g_agg[base + 1], acc[i][1] * cw * hv.y);
            atomicAdd(&g_agg[base + 2], acc[i][2] * cw * hv.z);
            atomicAdd(&g_agg[base + 3], acc[i][3] * cw * hv.w);
        }
    }
}

// ---------------- GIN branch kernels ----------------
__global__ void __launch_bounds__(256) segmax_kernel() {
    int idx = blockIdx.x * 256 + threadIdx.x;     // NT*HD
    int s = idx >> 7, f = idx & 127;
    int m = s >> 5, a = s & 31;
    int base = ((m << 8) + a) * HD + f;
    float v = g_x[base];
#pragma unroll
    for (int k = 1; k < 8; k++) v = fmaxf(v, g_x[base + k * 32 * HD]);
    g_xagg[idx] = v;
}

__global__ void __launch_bounds__(256) ginscatter_kernel(const int* __restrict__ eig,
                                                         const int* __restrict__ eag,
                                                         const float* __restrict__ bemb) {
    int idx = blockIdx.x * 256 + threadIdx.x;     // EGRAPH*HD
    int e = idx >> 7, f = idx & 127;
    int gr = eig[e], gc = eig[EGRAPH + e];
    float v = g_xagg[gr * HD + f] + bemb[eag[e] * HD + f];
    v = fmaxf(v, 0.f);
    atomicAdd(&g_magg[gc * HD + f], v);
}

__global__ void __launch_bounds__(256) ginpre_kernel(const float* __restrict__ geps, int l) {
    int idx = blockIdx.x * 256 + threadIdx.x;     // NT*HD
    float e = 1.f + geps[l];
    g_hg0[idx] = e * g_xagg[idx] + g_magg[idx];
}

// batchnorm over 8192 rows per column. SEL 0: g_hg1->g_hg2 ; SEL 1: g_hg3->g_hgf
template <int SEL>
__global__ void __launch_bounds__(256) bn_kernel(const float* __restrict__ gma,
                                                 const float* __restrict__ bta, int relu) {
    const float* X;
    float* Y;
    if constexpr (SEL == 0) { X = g_hg1; Y = g_hg2; }
    else                    { X = g_hg3; Y = g_hgf; }
    __shared__ float sred[256];
    int c = blockIdx.x, t = threadIdx.x;
    float v[32];
    float sum = 0.f;
#pragma unroll
    for (int i = 0; i < 32; i++) {
        v[i] = X[(t + (i << 8)) * HD + c];
        sum += v[i];
    }
    sred[t] = sum;
    __syncthreads();
    for (int off = 128; off; off >>= 1) {
        if (t < off) sred[t] += sred[t + off];
        __syncthreads();
    }
    float mu = sred[0] * (1.f / 8192.f);
    __syncthreads();
    float sq = 0.f;
#pragma unroll
    for (int i = 0; i < 32; i++) {
        float d = v[i] - mu;
        sq = fmaf(d, d, sq);
    }
    sred[t] = sq;
    __syncthreads();
    for (int off = 128; off; off >>= 1) {
        if (t < off) sred[t] += sred[t + off];
        __syncthreads();
    }
    float var = sred[0] * (1.f / 8192.f);
    float sc = rsqrtf(var + 1e-5f) * gma[c];
    float sh = bta[c];
#pragma unroll
    for (int i = 0; i < 32; i++) {
        float o = (v[i] - mu) * sc + sh;
        if (relu) o = fmaxf(o, 0.f);
        Y[(t + (i << 8)) * HD + c] = o;
    }
}

// x = relu(x + t2 + hgf[cnb]) (cnb structural)
__global__ void __launch_bounds__(256) combine_kernel() {
    int idx = blockIdx.x * 256 + threadIdx.x;     // NN*HD
    int n = idx >> 7, f = idx & 127;
    int s = ((n >> 8) << 5) | (n & 31);
    float v = g_x[idx] + g_t2[idx] + g_hgf[s * HD + f];
    g_x[idx] = fmaxf(v, 0.f);
}

// ---------------- pooling (max over 256 contiguous nodes/molecule) ----------------
__global__ void __launch_bounds__(256) pool_kernel() {
    int idx = blockIdx.x * 256 + threadIdx.x;     // NMOL*HD
    int m = idx >> 7, f = idx & 127;
    const float* p = g_x + (m << 8) * HD + f;
    float v0 = -1e30f, v1 = -1e30f, v2 = -1e30f, v3 = -1e30f;
#pragma unroll 4
    for (int j = 0; j < 256; j += 4) {
        v0 = fmaxf(v0, p[(j + 0) * HD]);
        v1 = fmaxf(v1, p[(j + 1) * HD]);
        v2 = fmaxf(v2, p[(j + 2) * HD]);
        v3 = fmaxf(v3, p[(j + 3) * HD]);
    }
    g_pool[idx] = fmaxf(fmaxf(v0, v1), fmaxf(v2, v3));
}

// ---------------- output head ----------------
__global__ void __launch_bounds__(128) final_kernel(const float* __restrict__ w1,
                                                    const float* __restrict__ b1,
                                                    const float* __restrict__ w2,
                                                    const float* __restrict__ b2,
                                                    float* __restrict__ out) {
    __shared__ float sp[128];
    __shared__ float sr[128];
    int m = blockIdx.x, t = threadIdx.x;
    sp[t] = g_pool[m * HD + t];
    __syncthreads();
    float acc = b1[t];
#pragma unroll 8
    for (int k = 0; k < 128; k++) acc = fmaf(sp[k], w1[k * HD + t], acc);
    sr[t] = fmaxf(acc, 0.f) * w2[t];
    __syncthreads();
    for (int off = 64; off; off >>= 1) {
        if (t < off) sr[t] += sr[t + off];
        __syncthreads();
    }
    if (t == 0) out[m] = sr[0] + b2[0];
}

// ---------------- host launcher ----------------
extern "C" void kernel_launch(void* const* d_in, const int* in_sizes, int n_in,
                              void* d_out, int out_size) {
    const int*   x_topo = (const int*)d_in[0];
    const float* pos    = (const float*)d_in[1];
    const int*   eic    = (const int*)d_in[2];
    const int*   eig    = (const int*)d_in[3];
    const int*   eag    = (const int*)d_in[4];
    const float* aemb   = (const float*)d_in[8];
    const float* lin1w  = (const float*)d_in[9];
    const float* mw1    = (const float*)d_in[10];
    const float* mb1    = (const float*)d_in[11];
    const float* mw2    = (const float*)d_in[12];
    const float* mb2    = (const float*)d_in[13];
    const float* lin2w  = (const float*)d_in[14];
    const float* lin2b  = (const float*)d_in[15];
    const float* linw   = (const float*)d_in[16];
    const float* linb   = (const float*)d_in[17];
    const float* bemb   = (const float*)d_in[18];
    const float* gw1    = (const float*)d_in[19];
    const float* gb1    = (const float*)d_in[20];
    const float* gw2    = (const float*)d_in[21];
    const float* gb2    = (const float*)d_in[22];
    const float* gbng   = (const float*)d_in[23];
    const float* gbnb   = (const float*)d_in[24];
    const float* bng    = (const float*)d_in[25];
    const float* bnb    = (const float*)d_in[26];
    const float* geps   = (const float*)d_in[27];
    const float* ow1    = (const float*)d_in[28];
    const float* ob1    = (const float*)d_in[29];
    const float* ow2    = (const float*)d_in[30];
    const float* ob2    = (const float*)d_in[31];
    float* out = (float*)d_out;

    cudaFuncSetAttribute(edge_kernel, cudaFuncAttributeMaxDynamicSharedMemorySize,
                         EDGE_SMEM_BYTES);

    eprep_kernel<<<ECONF / 256, 256>>>(eic, pos);
    initx_kernel<<<NN * HD / 256, 256>>>(x_topo, aemb);

    for (int l = 0; l < 4; l++) {
        // CFConv branch
        gemm_kernel<64, 0><<<NN / 64, 256>>>(lin1w + l * 128 * 64, nullptr, 128, 0);
        zero_agg_kernel<<<NN * FD / 1024, 256>>>();
        edge_kernel<<<ECONF / 128, 256, EDGE_SMEM_BYTES>>>(
            mw1 + l * GD * 64, mb1 + l * 64, mw2 + l * 64 * 64, mb2 + l * 64, eic);
        gemm_kernel<128, 1><<<NN / 64, 256>>>(lin2w + l * 64 * 128, lin2b + l * 128, 64, 2);
        gemm_kernel<128, 2><<<NN / 64, 256>>>(linw + l * 128 * 128, linb + l * 128, 128, 1);
        // GIN branch
        segmax_kernel<<<NT * HD / 256, 256>>>();
        zero_magg_kernel<<<NT * HD / 1024, 256>>>();
        ginscatter_kernel<<<EGRAPH * HD / 256, 256>>>(eig, eag, bemb + l * 10 * HD);
        ginpre_kernel<<<NT * HD / 256, 256>>>(geps, l);
        gemm_kernel<128, 3><<<NT / 64, 256>>>(gw1 + l * 128 * 128, gb1 + l * 128, 128, 1);
        bn_kernel<0><<<128, 256>>>(gbng + l * 128, gbnb + l * 128, 1);
        gemm_kernel<128, 4><<<NT / 64, 256>>>(gw2 + l * 128 * 128, gb2 + l * 128, 128, 1);
        bn_kernel<1><<<128, 256>>>(bng + l * 128, bnb + l * 128, 0);
        // x = relu(x + t2 + hgf[cnb])
        combine_kernel<<<NN * HD / 256, 256>>>();
    }

    pool_kernel<<<NMOL * HD / 256, 256>>>();
    final_kernel<<<NMOL, 128>>>(ow1, ob1, ow2, ob2, out);
}

// round 3
// speedup vs baseline: 1.1116x; 1.1116x over previous
#include <cuda_runtime.h>
#include <math.h>

// ---------------- problem constants ----------------
#define NN      65536      // nodes (conformer graph)
#define NT      8192       // topo nodes
#define ECONF   1048576
#define EGRAPH  32768
#define NMOL    256
#define HD      128
#define FD      64
#define GD      50

#define GSTEP   0.20408163265306123f   // 10/49
#define GC      (-12.005f)             // -0.5/(10/49)^2
#define PI10    0.31415926535897931f

typedef unsigned long long u64;

// ---------------- f32x2 packed-math helpers (sm_100+) ----------------
__device__ __forceinline__ u64 pack2(float a, float b) {
    u64 r; asm("mov.b64 %0, {%1, %2};" : "=l"(r) : "f"(a), "f"(b)); return r;
}
__device__ __forceinline__ float2 unpack2(u64 v) {
    float2 r; asm("mov.b64 {%0, %1}, %2;" : "=f"(r.x), "=f"(r.y) : "l"(v)); return r;
}
__device__ __forceinline__ u64 ffma2(u64 a, u64 b, u64 c) {
    u64 d; asm("fma.rn.f32x2 %0, %1, %2, %3;" : "=l"(d) : "l"(a), "l"(b), "l"(c)); return d;
}
__device__ __forceinline__ void red4(float* p, float a, float b, float c, float d) {
    asm volatile("red.global.add.v4.f32 [%0], {%1, %2, %3, %4};"
                 :: "l"(p), "f"(a), "f"(b), "f"(c), "f"(d) : "memory");
}

// ---------------- scratch (__device__ globals; no cudaMalloc) ----------------
__device__ float g_ew[ECONF];
__device__ float g_cwin[ECONF];
__device__ float g_x[NN * HD];
__device__ float g_h[NN * FD];
__device__ float g_agg[NN * FD];
__device__ float g_t1[NN * HD];
__device__ float g_t2[NN * HD];
__device__ float g_xagg[NT * HD];
__device__ float g_magg[NT * HD];
__device__ float g_hg0[NT * HD];
__device__ float g_hg1[NT * HD];
__device__ float g_hg2[NT * HD];
__device__ float g_hg3[NT * HD];
__device__ float g_hgf[NT * HD];
__device__ float g_pool[NMOL * HD];

// ---------------- edge precompute: distance + cosine window ----------------
__global__ void __launch_bounds__(256) eprep_kernel(const int* __restrict__ eic,
                                                    const float* __restrict__ pos) {
    int e = blockIdx.x * 256 + threadIdx.x;
    int r = eic[e], c = eic[ECONF + e];
    float dx = pos[r * 3 + 0] - pos[c * 3 + 0];
    float dy = pos[r * 3 + 1] - pos[c * 3 + 1];
    float dz = pos[r * 3 + 2] - pos[c * 3 + 2];
    float w = sqrtf(dx * dx + dy * dy + dz * dz + 1e-12f);
    g_ew[e] = w;
    g_cwin[e] = 0.5f * (cosf(w * PI10) + 1.0f);
}

// ---------------- x0 = atom_emb[x_topo][cnb] (cnb structural) ----------------
__global__ void __launch_bounds__(256) initx_kernel(const int* __restrict__ xt,
                                                    const float* __restrict__ aemb) {
    int idx = blockIdx.x * 256 + threadIdx.x;
    int n = idx >> 7, f = idx & 127;
    int s = ((n >> 8) << 5) | (n & 31);
    g_x[idx] = aemb[xt[s] * HD + f];
}

// ---------------- zero kernels ----------------
__global__ void __launch_bounds__(256) zero_agg_kernel() {
    int i = blockIdx.x * 256 + threadIdx.x;
    *(float4*)&g_agg[i << 2] = make_float4(0.f, 0.f, 0.f, 0.f);
}
__global__ void __launch_bounds__(256) zero_magg_kernel() {
    int i = blockIdx.x * 256 + threadIdx.x;
    *(float4*)&g_magg[i << 2] = make_float4(0.f, 0.f, 0.f, 0.f);
}

// ---------------- generic tiled fp32 GEMM: C[M,BN] = A[M,K] @ B[K,BN] ----------------
// SEL chooses (A, C) among device globals. mode: 0 none, 1 +bias, 2 +bias+relu.
// FFMA2: accumulator paired over the column dimension (B pairs free from SMEM).
template <int BN, int SEL>
__global__ void __launch_bounds__(256) gemm_kernel(const float* __restrict__ B,
                                                   const float* __restrict__ bias,
                                                   int K, int mode) {
    const float* A;
    float* C;
    if constexpr (SEL == 0) { A = g_x;   C = g_h;  }
    else if constexpr (SEL == 1) { A = g_agg; C = g_t1; }
    else if constexpr (SEL == 2) { A = g_t1;  C = g_t2; }
    else if constexpr (SEL == 3) { A = g_hg0; C = g_hg1; }
    else                         { A = g_hg2; C = g_hg3; }

    __shared__ float As[64 * 36];
    __shared__ float Bs[32 * BN];
    const int t = threadIdx.x;
    const int m0 = blockIdx.x * 64;
    const int tr = t >> 4, tc = t & 15;
    constexpr int NC = BN / 16;     // cols per thread (4 or 8)
    constexpr int NP = NC / 2;      // col pairs (2 or 4)
    u64 acc2[4][NP];
#pragma unroll
    for (int i = 0; i < 4; i++)
#pragma unroll
        for (int j = 0; j < NP; j++) acc2[i][j] = 0ull;

    for (int k0 = 0; k0 < K; k0 += 32) {
        __syncthreads();
#pragma unroll
        for (int q = 0; q < 2; q++) {
            int p = t + (q << 8);
            int r = p >> 3, kq = (p & 7) << 2;
            float4 v = *(const float4*)&A[(m0 + r) * K + k0 + kq];
            *(float4*)&As[r * 36 + kq] = v;
        }
#pragma unroll
        for (int q = 0; q < BN / 32; q++) {
            int p = t + (q << 8);
            int kk = p / (BN / 4), cc = (p % (BN / 4)) << 2;
            *(float4*)&Bs[kk * BN + cc] = *(const float4*)&B[(k0 + kk) * BN + cc];
        }
        __syncthreads();
#pragma unroll 8
        for (int kk = 0; kk < 32; kk++) {
            u64 ad[4];
#pragma unroll
            for (int i = 0; i < 4; i++) {
                float a = As[(tr * 4 + i) * 36 + kk];
                ad[i] = pack2(a, a);
            }
            ulonglong2 bp0 = *(const ulonglong2*)&Bs[kk * BN + (tc << 2)];
#pragma unroll
            for (int i = 0; i < 4; i++) {
                acc2[i][0] = ffma2(ad[i], bp0.x, acc2[i][0]);
                acc2[i][1] = ffma2(ad[i], bp0.y, acc2[i][1]);
            }
            if constexpr (BN == 128) {
                ulonglong2 bp1 = *(const ulonglong2*)&Bs[kk * BN + 64 + (tc << 2)];
#pragma unroll
                for (int i = 0; i < 4; i++) {
                    acc2[i][2] = ffma2(ad[i], bp1.x, acc2[i][2]);
                    acc2[i][3] = ffma2(ad[i], bp1.y, acc2[i][3]);
                }
            }
        }
    }
    float4 bb0 = make_float4(0.f, 0.f, 0.f, 0.f), bb1 = make_float4(0.f, 0.f, 0.f, 0.f);
    if (mode != 0) {
        bb0 = *(const float4*)&bias[tc << 2];
        if constexpr (BN == 128) bb1 = *(const float4*)&bias[64 + (tc << 2)];
    }
#pragma unroll
    for (int i = 0; i < 4; i++) {
        int r = m0 + tr * 4 + i;
        float2 q0 = unpack2(acc2[i][0]), q1 = unpack2(acc2[i][1]);
        float4 o0 = make_float4(q0.x + bb0.x, q0.y + bb0.y, q1.x + bb0.z, q1.y + bb0.w);
        if (mode == 2) {
            o0.x = fmaxf(o0.x, 0.f); o0.y = fmaxf(o0.y, 0.f);
            o0.z = fmaxf(o0.z, 0.f); o0.w = fmaxf(o0.w, 0.f);
        }
        *(float4*)&C[r * BN + (tc << 2)] = o0;
        if constexpr (BN == 128) {
            float2 q2 = unpack2(acc2[i][2]), q3 = unpack2(acc2[i][3]);
            float4 o1 = make_float4(q2.x + bb1.x, q2.y + bb1.y, q3.x + bb1.z, q3.y + bb1.w);
            if (mode == 2) {
                o1.x = fmaxf(o1.x, 0.f); o1.y = fmaxf(o1.y, 0.f);
                o1.z = fmaxf(o1.z, 0.f); o1.w = fmaxf(o1.w, 0.f);
            }
            *(float4*)&C[r * BN + 64 + (tc << 2)] = o1;
        }
    }
}

// ---------------- fused CFConv edge kernel (FFMA2) ----------------
// CTA = 256 threads / 128 edges. gauss -> relu(g@W1+b1) -> (u@W2+b2)*cwin
// -> gather h[row], red.v4 scatter into agg[col].
// Accumulator paired over the EDGE dimension (activation pairs free from SMEM).
#define SM_W1  0
#define SM_W2  3200
#define SM_EA  7296
#define SM_U   13696       // 64 rows x 132 (padded)
#define SM_B1  22144
#define SM_B2  22208
#define SM_EW  22272
#define SM_CW  22400
#define SM_RC  22528       // int row[128], col[128]
#define EDGE_SMEM_FLOATS 22784
#define EDGE_SMEM_BYTES  (EDGE_SMEM_FLOATS * 4)

__global__ void __launch_bounds__(256) edge_kernel(const float* __restrict__ W1,
                                                   const float* __restrict__ B1,
                                                   const float* __restrict__ W2,
                                                   const float* __restrict__ B2,
                                                   const int* __restrict__ eic) {
    extern __shared__ float sm[];
    float* sW1 = sm + SM_W1;
    float* sW2 = sm + SM_W2;
    float* sEA = sm + SM_EA;
    float* sU  = sm + SM_U;
    float* sB1 = sm + SM_B1;
    float* sB2 = sm + SM_B2;
    float* sEW = sm + SM_EW;
    float* sCW = sm + SM_CW;
    int*   sRC = (int*)(sm + SM_RC);

    const int t = threadIdx.x;
    const int e0 = blockIdx.x * 128;
#pragma unroll 4
    for (int i = t; i < 3200; i += 256) sW1[i] = W1[i];
#pragma unroll 4
    for (int i = t; i < 4096; i += 256) sW2[i] = W2[i];
    if (t < 64) { sB1[t] = B1[t]; sB2[t] = B2[t]; }
    if (t < 128) {
        sRC[t]       = eic[e0 + t];
        sRC[128 + t] = eic[ECONF + e0 + t];
        sEW[t] = g_ew[e0 + t];
        sCW[t] = g_cwin[e0 + t];
    }
    __syncthreads();

    // gaussians: sEA[k][e]
#pragma unroll 1
    for (int i = t; i < GD * 128; i += 256) {
        int k = i >> 7, e = i & 127;
        float d = sEW[e] - (float)k * GSTEP;
        sEA[i] = expf(GC * d * d);
    }
    __syncthreads();

    const int tf = t & 15, te = t >> 4;

    // GEMM1: u[e][f] = relu(b1[f] + sum_k ea[e][k] * W1[k][f])
    {
        u64 acc2[4][4];
        {
            float4 bi = *(const float4*)&sB1[tf << 2];
            u64 b0 = pack2(bi.x, bi.x), b1 = pack2(bi.y, bi.y);
            u64 b2 = pack2(bi.z, bi.z), b3 = pack2(bi.w, bi.w);
#pragma unroll
            for (int ep = 0; ep < 4; ep++) {
                acc2[ep][0] = b0; acc2[ep][1] = b1;
                acc2[ep][2] = b2; acc2[ep][3] = b3;
            }
        }
#pragma unroll 5
        for (int k = 0; k < GD; k++) {
            ulonglong2 A0 = *(const ulonglong2*)&sEA[(k << 7) + (te << 3)];
            ulonglong2 A1 = *(const ulonglong2*)&sEA[(k << 7) + (te << 3) + 4];
            u64 ap[4] = {A0.x, A0.y, A1.x, A1.y};
            float4 b = *(const float4*)&sW1[k * 64 + (tf << 2)];
            u64 bd[4] = {pack2(b.x, b.x), pack2(b.y, b.y), pack2(b.z, b.z), pack2(b.w, b.w)};
#pragma unroll
            for (int ep = 0; ep < 4; ep++) {
                acc2[ep][0] = ffma2(ap[ep], bd[0], acc2[ep][0]);
                acc2[ep][1] = ffma2(ap[ep], bd[1], acc2[ep][1]);
                acc2[ep][2] = ffma2(ap[ep], bd[2], acc2[ep][2]);
                acc2[ep][3] = ffma2(ap[ep], bd[3], acc2[ep][3]);
            }
        }
#pragma unroll
        for (int j = 0; j < 4; j++) {
            float2 p0 = unpack2(acc2[0][j]), p1 = unpack2(acc2[1][j]);
            float2 p2 = unpack2(acc2[2][j]), p3 = unpack2(acc2[3][j]);
            float4 v0 = make_float4(fmaxf(p0.x, 0.f), fmaxf(p0.y, 0.f),
                                    fmaxf(p1.x, 0.f), fmaxf(p1.y, 0.f));
            float4 v1 = make_float4(fmaxf(p2.x, 0.f), fmaxf(p2.y, 0.f),
                                    fmaxf(p3.x, 0.f), fmaxf(p3.y, 0.f));
            *(float4*)&sU[((tf << 2) + j) * 132 + (te << 3)] = v0;
            *(float4*)&sU[((tf << 2) + j) * 132 + (te << 3) + 4] = v1;
        }
    }
    __syncthreads();

    // GEMM2: wf[e][f] = (b2[f] + sum_k u[e][k]*W2[k][f]) * cwin[e]; then scatter
    {
        u64 acc2[4][4];
        {
            float4 bi = *(const float4*)&sB2[tf << 2];
            u64 b0 = pack2(bi.x, bi.x), b1 = pack2(bi.y, bi.y);
            u64 b2 = pack2(bi.z, bi.z), b3 = pack2(bi.w, bi.w);
#pragma unroll
            for (int ep = 0; ep < 4; ep++) {
                acc2[ep][0] = b0; acc2[ep][1] = b1;
                acc2[ep][2] = b2; acc2[ep][3] = b3;
            }
        }
#pragma unroll 4
        for (int k = 0; k < 64; k++) {
            ulonglong2 A0 = *(const ulonglong2*)&sU[k * 132 + (te << 3)];
            ulonglong2 A1 = *(const ulonglong2*)&sU[k * 132 + (te << 3) + 4];
            u64 ap[4] = {A0.x, A0.y, A1.x, A1.y};
            float4 b = *(const float4*)&sW2[k * 64 + (tf << 2)];
            u64 bd[4] = {pack2(b.x, b.x), pack2(b.y, b.y), pack2(b.z, b.z), pack2(b.w, b.w)};
#pragma unroll
            for (int ep = 0; ep < 4; ep++) {
                acc2[ep][0] = ffma2(ap[ep], bd[0], acc2[ep][0]);
                acc2[ep][1] = ffma2(ap[ep], bd[1], acc2[ep][1]);
                acc2[ep][2] = ffma2(ap[ep], bd[2], acc2[ep][2]);
                acc2[ep][3] = ffma2(ap[ep], bd[3], acc2[ep][3]);
            }
        }
#pragma unroll
        for (int ep = 0; ep < 4; ep++) {
            float2 u0 = unpack2(acc2[ep][0]), u1 = unpack2(acc2[ep][1]);
            float2 u2 = unpack2(acc2[ep][2]), u3 = unpack2(acc2[ep][3]);
#pragma unroll
            for (int hh = 0; hh < 2; hh++) {
                int e = (te << 3) + ep * 2 + hh;
                float w0 = hh ? u0.y : u0.x;
                float w1 = hh ? u1.y : u1.x;
                float w2 = hh ? u2.y : u2.x;
                float w3 = hh ? u3.y : u3.x;
                float cw = sCW[e];
                int r = sRC[e], c = sRC[128 + e];
                float4 hv = *(const float4*)&g_h[r * 64 + (tf << 2)];
                red4(&g_agg[c * 64 + (tf << 2)],
                     w0 * cw * hv.x, w1 * cw * hv.y, w2 * cw * hv.z, w3 * cw * hv.w);
            }
        }
    }
}

// ---------------- GIN branch kernels ----------------
__global__ void __launch_bounds__(256) segmax_kernel() {
    int idx = blockIdx.x * 256 + threadIdx.x;     // NT*HD
    int s = idx >> 7, f = idx & 127;
    int m = s >> 5, a = s & 31;
    int base = ((m << 8) + a) * HD + f;
    float v = g_x[base];
#pragma unroll
    for (int k = 1; k < 8; k++) v = fmaxf(v, g_x[base + k * 32 * HD]);
    g_xagg[idx] = v;
}

__global__ void __launch_bounds__(256) ginscatter_kernel(const int* __restrict__ eig,
                                                         const int* __restrict__ eag,
                                                         const float* __restrict__ bemb) {
    int idx = blockIdx.x * 256 + threadIdx.x;     // EGRAPH*HD
    int e = idx >> 7, f = idx & 127;
    int gr = eig[e], gc = eig[EGRAPH + e];
    float v = g_xagg[gr * HD + f] + bemb[eag[e] * HD + f];
    v = fmaxf(v, 0.f);
    atomicAdd(&g_magg[gc * HD + f], v);
}

__global__ void __launch_bounds__(256) ginpre_kernel(const float* __restrict__ geps, int l) {
    int idx = blockIdx.x * 256 + threadIdx.x;     // NT*HD
    float e = 1.f + geps[l];
    g_hg0[idx] = e * g_xagg[idx] + g_magg[idx];
}

// batchnorm over 8192 rows per column. SEL 0: g_hg1->g_hg2 ; SEL 1: g_hg3->g_hgf
template <int SEL>
__global__ void __launch_bounds__(256) bn_kernel(const float* __restrict__ gma,
                                                 const float* __restrict__ bta, int relu) {
    const float* X;
    float* Y;
    if constexpr (SEL == 0) { X = g_hg1; Y = g_hg2; }
    else                    { X = g_hg3; Y = g_hgf; }
    __shared__ float sred[256];
    int c = blockIdx.x, t = threadIdx.x;
    float v[32];
    float sum = 0.f;
#pragma unroll
    for (int i = 0; i < 32; i++) {
        v[i] = X[(t + (i << 8)) * HD + c];
        sum += v[i];
    }
    sred[t] = sum;
    __syncthreads();
    for (int off = 128; off; off >>= 1) {
        if (t < off) sred[t] += sred[t + off];
        __syncthreads();
    }
    float mu = sred[0] * (1.f / 8192.f);
    __syncthreads();
    float sq = 0.f;
#pragma unroll
    for (int i = 0; i < 32; i++) {
        float d = v[i] - mu;
        sq = fmaf(d, d, sq);
    }
    sred[t] = sq;
    __syncthreads();
    for (int off = 128; off; off >>= 1) {
        if (t < off) sred[t] += sred[t + off];
        __syncthreads();
    }
    float var = sred[0] * (1.f / 8192.f);
    float sc = rsqrtf(var + 1e-5f) * gma[c];
    float sh = bta[c];
#pragma unroll
    for (int i = 0; i < 32; i++) {
        float o = (v[i] - mu) * sc + sh;
        if (relu) o = fmaxf(o, 0.f);
        Y[(t + (i << 8)) * HD + c] = o;
    }
}

// x = relu(x + t2 + hgf[cnb]) (cnb structural)
__global__ void __launch_bounds__(256) combine_kernel() {
    int idx = blockIdx.x * 256 + threadIdx.x;     // NN*HD
    int n = idx >> 7, f = idx & 127;
    int s = ((n >> 8) << 5) | (n & 31);
    float v = g_x[idx] + g_t2[idx] + g_hgf[s * HD + f];
    g_x[idx] = fmaxf(v, 0.f);
}

// ---------------- pooling (max over 256 contiguous nodes/molecule) ----------------
__global__ void __launch_bounds__(256) pool_kernel() {
    int idx = blockIdx.x * 256 + threadIdx.x;     // NMOL*HD
    int m = idx >> 7, f = idx & 127;
    const float* p = g_x + (m << 8) * HD + f;
    float v0 = -1e30f, v1 = -1e30f, v2 = -1e30f, v3 = -1e30f;
#pragma unroll 4
    for (int j = 0; j < 256; j += 4) {
        v0 = fmaxf(v0, p[(j + 0) * HD]);
        v1 = fmaxf(v1, p[(j + 1) * HD]);
        v2 = fmaxf(v2, p[(j + 2) * HD]);
        v3 = fmaxf(v3, p[(j + 3) * HD]);
    }
    g_pool[idx] = fmaxf(fmaxf(v0, v1), fmaxf(v2, v3));
}

// ---------------- output head ----------------
__global__ void __launch_bounds__(128) final_kernel(const float* __restrict__ w1,
                                                    const float* __restrict__ b1,
                                                    const float* __restrict__ w2,
                                                    const float* __restrict__ b2,
                                                    float* __restrict__ out) {
    __shared__ float sp[128];
    __shared__ float sr[128];
    int m = blockIdx.x, t = threadIdx.x;
    sp[t] = g_pool[m * HD + t];
    __syncthreads();
    float acc = b1[t];
#pragma unroll 8
    for (int k = 0; k < 128; k++) acc = fmaf(sp[k], w1[k * HD + t], acc);
    sr[t] = fmaxf(acc, 0.f) * w2[t];
    __syncthreads();
    for (int off = 64; off; off >>= 1) {
        if (t < off) sr[t] += sr[t + off];
        __syncthreads();
    }
    if (t == 0) out[m] = sr[0] + b2[0];
}

// ---------------- host launcher ----------------
extern "C" void kernel_launch(void* const* d_in, const int* in_sizes, int n_in,
                              void* d_out, int out_size) {
    const int*   x_topo = (const int*)d_in[0];
    const float* pos    = (const float*)d_in[1];
    const int*   eic    = (const int*)d_in[2];
    const int*   eig    = (const int*)d_in[3];
    const int*   eag    = (const int*)d_in[4];
    const float* aemb   = (const float*)d_in[8];
    const float* lin1w  = (const float*)d_in[9];
    const float* mw1    = (const float*)d_in[10];
    const float* mb1    = (const float*)d_in[11];
    const float* mw2    = (const float*)d_in[12];
    const float* mb2    = (const float*)d_in[13];
    const float* lin2w  = (const float*)d_in[14];
    const float* lin2b  = (const float*)d_in[15];
    const float* linw   = (const float*)d_in[16];
    const float* linb   = (const float*)d_in[17];
    const float* bemb   = (const float*)d_in[18];
    const float* gw1    = (const float*)d_in[19];
    const float* gb1    = (const float*)d_in[20];
    const float* gw2    = (const float*)d_in[21];
    const float* gb2    = (const float*)d_in[22];
    const float* gbng   = (const float*)d_in[23];
    const float* gbnb   = (const float*)d_in[24];
    const float* bng    = (const float*)d_in[25];
    const float* bnb    = (const float*)d_in[26];
    const float* geps   = (const float*)d_in[27];
    const float* ow1    = (const float*)d_in[28];
    const float* ob1    = (const float*)d_in[29];
    const float* ow2    = (const float*)d_in[30];
    const float* ob2    = (const float*)d_in[31];
    float* out = (float*)d_out;

    cudaFuncSetAttribute(edge_kernel, cudaFuncAttributeMaxDynamicSharedMemorySize,
                         EDGE_SMEM_BYTES);

    eprep_kernel<<<ECONF / 256, 256>>>(eic, pos);
    initx_kernel<<<NN * HD / 256, 256>>>(x_topo, aemb);

    for (int l = 0; l < 4; l++) {
        // CFConv branch
        gemm_kernel<64, 0><<<NN / 64, 256>>>(lin1w + l * 128 * 64, nullptr, 128, 0);
        zero_agg_kernel<<<NN * FD / 1024, 256>>>();
        edge_kernel<<<ECONF / 128, 256, EDGE_SMEM_BYTES>>>(
            mw1 + l * GD * 64, mb1 + l * 64, mw2 + l * 64 * 64, mb2 + l * 64, eic);
        gemm_kernel<128, 1><<<NN / 64, 256>>>(lin2w + l * 64 * 128, lin2b + l * 128, 64, 2);
        gemm_kernel<128, 2><<<NN / 64, 256>>>(linw + l * 128 * 128, linb + l * 128, 128, 1);
        // GIN branch
        segmax_kernel<<<NT * HD / 256, 256>>>();
        zero_magg_kernel<<<NT * HD / 1024, 256>>>();
        ginscatter_kernel<<<EGRAPH * HD / 256, 256>>>(eig, eag, bemb + l * 10 * HD);
        ginpre_kernel<<<NT * HD / 256, 256>>>(geps, l);
        gemm_kernel<128, 3><<<NT / 64, 256>>>(gw1 + l * 128 * 128, gb1 + l * 128, 128, 1);
        bn_kernel<0><<<128, 256>>>(gbng + l * 128, gbnb + l * 128, 1);
        gemm_kernel<128, 4><<<NT / 64, 256>>>(gw2 + l * 128 * 128, gb2 + l * 128, 128, 1);
        bn_kernel<1><<<128, 256>>>(bng + l * 128, bnb + l * 128, 0);
        // x = relu(x + t2 + hgf[cnb])
        combine_kernel<<<NN * HD / 256, 256>>>();
    }

    pool_kernel<<<NMOL * HD / 256, 256>>>();
    final_kernel<<<NMOL, 128>>>(ow1, ob1, ow2, ob2, out);
}

// round 4
// speedup vs baseline: 1.3553x; 1.2192x over previous
#include <cuda_runtime.h>
#include <math.h>

// ---------------- problem constants ----------------
#define NN      65536      // nodes (conformer graph)
#define NT      8192       // topo nodes
#define ECONF   1048576
#define EGRAPH  32768
#define NMOL    256
#define HD      128
#define FD      64
#define GD      50

#define GSTEP   0.20408163265306123f   // 10/49
#define PI10    0.31415926535897931f

typedef unsigned long long u64;
typedef unsigned int u32;

// ---------------- f32x2 packed-math helpers (sm_100+) ----------------
__device__ __forceinline__ u64 pack2(float a, float b) {
    u64 r; asm("mov.b64 %0, {%1, %2};" : "=l"(r) : "f"(a), "f"(b)); return r;
}
__device__ __forceinline__ float2 unpack2(u64 v) {
    float2 r; asm("mov.b64 {%0, %1}, %2;" : "=f"(r.x), "=f"(r.y) : "l"(v)); return r;
}
__device__ __forceinline__ u64 ffma2(u64 a, u64 b, u64 c) {
    u64 d; asm("fma.rn.f32x2 %0, %1, %2, %3;" : "=l"(d) : "l"(a), "l"(b), "l"(c)); return d;
}
__device__ __forceinline__ void red2(float* p, float a, float b) {
    asm volatile("red.global.add.v2.f32 [%0], {%1, %2};"
                 :: "l"(p), "f"(a), "f"(b) : "memory");
}
// tf32 round-to-nearest (unbiased)
__device__ __forceinline__ float tf32r(float x) {
    u32 u_; asm("cvt.rna.tf32.f32 %0, %1;" : "=r"(u_) : "f"(x));
    return __uint_as_float(u_);
}
// m16n8k8 tf32 MMA, fp32 accumulate
__device__ __forceinline__ void mma_tf32(float* d, u32 a0, u32 a1, u32 a2, u32 a3,
                                         u32 b0, u32 b1) {
    asm("mma.sync.aligned.m16n8k8.row.col.f32.tf32.tf32.f32 "
        "{%0,%1,%2,%3}, {%4,%5,%6,%7}, {%8,%9}, {%0,%1,%2,%3};"
        : "+f"(d[0]), "+f"(d[1]), "+f"(d[2]), "+f"(d[3])
        : "r"(a0), "r"(a1), "r"(a2), "r"(a3), "r"(b0), "r"(b1));
}

// ---------------- scratch (__device__ globals; no cudaMalloc) ----------------
__device__ float g_ew[ECONF];
__device__ float g_cwin[ECONF];
__device__ float g_x[NN * HD];
__device__ float g_h[NN * FD];
__device__ float g_agg[NN * FD];
__device__ float g_t1[NN * HD];
__device__ float g_t2[NN * HD];
__device__ float g_xagg[NT * HD];
__device__ float g_magg[NT * HD];
__device__ float g_hg0[NT * HD];
__device__ float g_hg1[NT * HD];
__device__ float g_hg2[NT * HD];
__device__ float g_hg3[NT * HD];
__device__ float g_hgf[NT * HD];
__device__ float g_pool[NMOL * HD];

// ---------------- edge precompute: distance + cosine window ----------------
__global__ void __launch_bounds__(256) eprep_kernel(const int* __restrict__ eic,
                                                    const float* __restrict__ pos) {
    int e = blockIdx.x * 256 + threadIdx.x;
    int r = eic[e], c = eic[ECONF + e];
    float dx = pos[r * 3 + 0] - pos[c * 3 + 0];
    float dy = pos[r * 3 + 1] - pos[c * 3 + 1];
    float dz = pos[r * 3 + 2] - pos[c * 3 + 2];
    float w = sqrtf(dx * dx + dy * dy + dz * dz + 1e-12f);
    g_ew[e] = w;
    g_cwin[e] = 0.5f * (cosf(w * PI10) + 1.0f);
}

// ---------------- x0 = atom_emb[x_topo][cnb] (cnb structural) ----------------
__global__ void __launch_bounds__(256) initx_kernel(const int* __restrict__ xt,
                                                    const float* __restrict__ aemb) {
    int idx = blockIdx.x * 256 + threadIdx.x;
    int n = idx >> 7, f = idx & 127;
    int s = ((n >> 8) << 5) | (n & 31);
    g_x[idx] = aemb[xt[s] * HD + f];
}

// ---------------- zero kernels ----------------
__global__ void __launch_bounds__(256) zero_agg_kernel() {
    int i = blockIdx.x * 256 + threadIdx.x;
    *(float4*)&g_agg[i << 2] = make_float4(0.f, 0.f, 0.f, 0.f);
}
__global__ void __launch_bounds__(256) zero_magg_kernel() {
    int i = blockIdx.x * 256 + threadIdx.x;
    *(float4*)&g_magg[i << 2] = make_float4(0.f, 0.f, 0.f, 0.f);
}

// ---------------- generic tiled fp32 GEMM (FFMA2): C[M,BN] = A[M,K] @ B[K,BN] ----------------
template <int BN, int SEL>
__global__ void __launch_bounds__(256) gemm_kernel(const float* __restrict__ B,
                                                   const float* __restrict__ bias,
                                                   int K, int mode) {
    const float* A;
    float* C;
    if constexpr (SEL == 0) { A = g_x;   C = g_h;  }
    else if constexpr (SEL == 1) { A = g_agg; C = g_t1; }
    else if constexpr (SEL == 2) { A = g_t1;  C = g_t2; }
    else if constexpr (SEL == 3) { A = g_hg0; C = g_hg1; }
    else                         { A = g_hg2; C = g_hg3; }

    __shared__ float As[64 * 36];
    __shared__ float Bs[32 * BN];
    const int t = threadIdx.x;
    const int m0 = blockIdx.x * 64;
    const int tr = t >> 4, tc = t & 15;
    constexpr int NC = BN / 16;
    constexpr int NP = NC / 2;
    u64 acc2[4][NP];
#pragma unroll
    for (int i = 0; i < 4; i++)
#pragma unroll
        for (int j = 0; j < NP; j++) acc2[i][j] = 0ull;

    for (int k0 = 0; k0 < K; k0 += 32) {
        __syncthreads();
#pragma unroll
        for (int q = 0; q < 2; q++) {
            int p = t + (q << 8);
            int r = p >> 3, kq = (p & 7) << 2;
            float4 v = *(const float4*)&A[(m0 + r) * K + k0 + kq];
            *(float4*)&As[r * 36 + kq] = v;
        }
#pragma unroll
        for (int q = 0; q < BN / 32; q++) {
            int p = t + (q << 8);
            int kk = p / (BN / 4), cc = (p % (BN / 4)) << 2;
            *(float4*)&Bs[kk * BN + cc] = *(const float4*)&B[(k0 + kk) * BN + cc];
        }
        __syncthreads();
#pragma unroll 8
        for (int kk = 0; kk < 32; kk++) {
            u64 ad[4];
#pragma unroll
            for (int i = 0; i < 4; i++) {
                float a = As[(tr * 4 + i) * 36 + kk];
                ad[i] = pack2(a, a);
            }
            ulonglong2 bp0 = *(const ulonglong2*)&Bs[kk * BN + (tc << 2)];
#pragma unroll
            for (int i = 0; i < 4; i++) {
                acc2[i][0] = ffma2(ad[i], bp0.x, acc2[i][0]);
                acc2[i][1] = ffma2(ad[i], bp0.y, acc2[i][1]);
            }
            if constexpr (BN == 128) {
                ulonglong2 bp1 = *(const ulonglong2*)&Bs[kk * BN + 64 + (tc << 2)];
#pragma unroll
                for (int i = 0; i < 4; i++) {
                    acc2[i][2] = ffma2(ad[i], bp1.x, acc2[i][2]);
                    acc2[i][3] = ffma2(ad[i], bp1.y, acc2[i][3]);
                }
            }
        }
    }
    float4 bb0 = make_float4(0.f, 0.f, 0.f, 0.f), bb1 = make_float4(0.f, 0.f, 0.f, 0.f);
    if (mode != 0) {
        bb0 = *(const float4*)&bias[tc << 2];
        if constexpr (BN == 128) bb1 = *(const float4*)&bias[64 + (tc << 2)];
    }
#pragma unroll
    for (int i = 0; i < 4; i++) {
        int r = m0 + tr * 4 + i;
        float2 q0 = unpack2(acc2[i][0]), q1 = unpack2(acc2[i][1]);
        float4 o0 = make_float4(q0.x + bb0.x, q0.y + bb0.y, q1.x + bb0.z, q1.y + bb0.w);
        if (mode == 2) {
            o0.x = fmaxf(o0.x, 0.f); o0.y = fmaxf(o0.y, 0.f);
            o0.z = fmaxf(o0.z, 0.f); o0.w = fmaxf(o0.w, 0.f);
        }
        *(float4*)&C[r * BN + (tc << 2)] = o0;
        if constexpr (BN == 128) {
            float2 q2 = unpack2(acc2[i][2]), q3 = unpack2(acc2[i][3]);
            float4 o1 = make_float4(q2.x + bb1.x, q2.y + bb1.y, q3.x + bb1.z, q3.y + bb1.w);
            if (mode == 2) {
                o1.x = fmaxf(o1.x, 0.f); o1.y = fmaxf(o1.y, 0.f);
                o1.z = fmaxf(o1.z, 0.f); o1.w = fmaxf(o1.w, 0.f);
            }
            *(float4*)&C[r * BN + 64 + (tc << 2)] = o1;
        }
    }
}

// ---------------- fused CFConv edge kernel: recurrence gaussians + tf32 MMA ----------------
// CTA = 256 threads / 128 edges. 8 warps, each owns 16 edge rows.
// SMEM floats layout:
#define ESTR 76                 // activation row stride (conflict-free: 76%32=12)
#define WSTR 68                 // weight row stride (68%32=4)
#define SEA_OFF 0               // 128*76 = 9728   (aliased by u after GEMM1)
#define SW1_OFF 9728            // 56*68 = 3808
#define SW2_OFF 13536           // 64*68 = 4352
#define SB1_OFF 17888           // 64
#define SB2_OFF 17952           // 64
#define SEW_OFF 18016           // 128
#define SCW_OFF 18144           // 128
#define SRC_OFF 18272           // 256 ints
#define EDGE_SMEM_FLOATS 18528
#define EDGE_SMEM_BYTES  (EDGE_SMEM_FLOATS * 4)

__global__ void __launch_bounds__(256) edge_kernel(const float* __restrict__ W1,
                                                   const float* __restrict__ B1,
                                                   const float* __restrict__ W2,
                                                   const float* __restrict__ B2,
                                                   const int* __restrict__ eic) {
    extern __shared__ float sm[];
    float* sEA = sm + SEA_OFF;
    float* sW1 = sm + SW1_OFF;
    float* sW2 = sm + SW2_OFF;
    float* sB1 = sm + SB1_OFF;
    float* sB2 = sm + SB2_OFF;
    float* sEW = sm + SEW_OFF;
    float* sCW = sm + SCW_OFF;
    int*   sRC = (int*)(sm + SRC_OFF);

    const int t = threadIdx.x;
    const int e0 = blockIdx.x * 128;

    // ---- stage weights (tf32-rounded), biases, edge meta ----
#pragma unroll 4
    for (int i = t; i < 56 * 64; i += 256) {
        int k = i >> 6, n = i & 63;
        float v = (k < GD) ? W1[k * 64 + n] : 0.f;
        sW1[k * WSTR + n] = tf32r(v);
    }
#pragma unroll 4
    for (int i = t; i < 64 * 64; i += 256) {
        int k = i >> 6, n = i & 63;
        sW2[k * WSTR + n] = tf32r(W2[i]);
    }
    if (t < 64) { sB1[t] = B1[t]; sB2[t] = B2[t]; }
    if (t < 128) {
        sRC[t]       = eic[e0 + t];
        sRC[128 + t] = eic[ECONF + e0 + t];
        sEW[t] = g_ew[e0 + t];
        sCW[t] = g_cwin[e0 + t];
    }

    // ---- zero gaussian rows (cols 0..55), 2 threads/edge ----
    {
        int e = t >> 1, hf = t & 1;
        float* row = sEA + e * ESTR + 28 * hf;
#pragma unroll
        for (int i = 0; i < 7; i++)
            *(float4*)(row + 4 * i) = make_float4(0.f, 0.f, 0.f, 0.f);
    }
    __syncthreads();

    // ---- windowed gaussian recurrence: 2 exps per thread, ~16 bins/edge ----
    {
        int e = t >> 1, hf = t & 1;
        float w = sEW[e];
        int kc = __float2int_rn(w * 4.9f);
        kc = min(max(kc, 0), GD - 1);
        float dc = w - (float)kc * GSTEP;
        float gc = __expf(-12.005f * dc * dc);
        const float q = 0.36787944117144233f;   // exp(-1)
        float* row = sEA + e * ESTR;
        if (hf == 0) {
            // center + descending k
            row[kc] = tf32r(gc);
            float g = gc;
            float r = __expf(-4.9f * dc - 0.5f);
#pragma unroll
            for (int i = 1; i <= 7; i++) {
                g *= r; r *= q;
                int k = kc - i;
                if (k >= 0) row[k] = tf32r(g);
            }
        } else {
            // ascending k (guarded: clamped-kc case never stores)
            float g = gc;
            float r = __expf(4.9f * dc - 0.5f);
#pragma unroll
            for (int i = 1; i <= 8; i++) {
                g *= r; r *= q;
                int k = kc + i;
                if (k <= GD - 1) row[k] = tf32r(g);
            }
        }
    }
    __syncthreads();

    // ---- warp/fragment coordinates ----
    const int lane = t & 31, wp = t >> 5;
    const int gid = lane >> 2, tid4 = lane & 3;
    const int er0 = wp * 16 + gid;   // rows for c0/c1
    const int er1 = er0 + 8;         // rows for c2/c3

    float d[8][4];
#pragma unroll
    for (int ns = 0; ns < 8; ns++)
#pragma unroll
        for (int j = 0; j < 4; j++) d[ns][j] = 0.f;

    // ---- GEMM1: u[128,64] = ea[128,56] @ W1[56,64] ----
    {
        const float* A0 = sEA + er0 * ESTR;
        const float* A1 = sEA + er1 * ESTR;
#pragma unroll
        for (int ks = 0; ks < 7; ks++) {
            int kb = ks * 8;
            u32 a0 = __float_as_uint(A0[kb + tid4]);
            u32 a1 = __float_as_uint(A1[kb + tid4]);
            u32 a2 = __float_as_uint(A0[kb + tid4 + 4]);
            u32 a3 = __float_as_uint(A1[kb + tid4 + 4]);
            const float* Bk0 = sW1 + (kb + tid4) * WSTR + gid;
            const float* Bk1 = Bk0 + 4 * WSTR;
#pragma unroll
            for (int ns = 0; ns < 8; ns++) {
                u32 b0 = __float_as_uint(Bk0[ns * 8]);
                u32 b1 = __float_as_uint(Bk1[ns * 8]);
                mma_tf32(d[ns], a0, a1, a2, a3, b0, b1);
            }
        }
    }
    __syncwarp();
    // u = relu(d + b1), tf32-rounded, stored in-place over sEA (rows warp-private)
#pragma unroll
    for (int ns = 0; ns < 8; ns++) {
        int n = ns * 8 + 2 * tid4;
        float bv0 = sB1[n], bv1 = sB1[n + 1];
        float2 u0 = make_float2(tf32r(fmaxf(d[ns][0] + bv0, 0.f)),
                                tf32r(fmaxf(d[ns][1] + bv1, 0.f)));
        float2 u1 = make_float2(tf32r(fmaxf(d[ns][2] + bv0, 0.f)),
                                tf32r(fmaxf(d[ns][3] + bv1, 0.f)));
        *(float2*)(sEA + er0 * ESTR + n) = u0;
        *(float2*)(sEA + er1 * ESTR + n) = u1;
    }
    __syncwarp();

    // ---- GEMM2: wf[128,64] = u[128,64] @ W2[64,64] ----
#pragma unroll
    for (int ns = 0; ns < 8; ns++)
#pragma unroll
        for (int j = 0; j < 4; j++) d[ns][j] = 0.f;
    {
        const float* A0 = sEA + er0 * ESTR;
        const float* A1 = sEA + er1 * ESTR;
#pragma unroll
        for (int ks = 0; ks < 8; ks++) {
            int kb = ks * 8;
            u32 a0 = __float_as_uint(A0[kb + tid4]);
            u32 a1 = __float_as_uint(A1[kb + tid4]);
            u32 a2 = __float_as_uint(A0[kb + tid4 + 4]);
            u32 a3 = __float_as_uint(A1[kb + tid4 + 4]);
            const float* Bk0 = sW2 + (kb + tid4) * WSTR + gid;
            const float* Bk1 = Bk0 + 4 * WSTR;
#pragma unroll
            for (int ns = 0; ns < 8; ns++) {
                u32 b0 = __float_as_uint(Bk0[ns * 8]);
                u32 b1 = __float_as_uint(Bk1[ns * 8]);
                mma_tf32(d[ns], a0, a1, a2, a3, b0, b1);
            }
        }
    }

    // ---- epilogue: (d + b2)*cwin * h[row] -> red.v2 into agg[col] ----
    {
        float cw0 = sCW[er0], cw1 = sCW[er1];
        int r0 = sRC[er0], c0 = sRC[128 + er0];
        int r1 = sRC[er1], c1 = sRC[128 + er1];
#pragma unroll
        for (int ns = 0; ns < 8; ns++) {
            int n = ns * 8 + 2 * tid4;
            float bv0 = sB2[n], bv1 = sB2[n + 1];
            float2 h0 = *(const float2*)&g_h[r0 * 64 + n];
            float2 h1 = *(const float2*)&g_h[r1 * 64 + n];
            red2(&g_agg[c0 * 64 + n],
                 (d[ns][0] + bv0) * cw0 * h0.x, (d[ns][1] + bv1) * cw0 * h0.y);
            red2(&g_agg[c1 * 64 + n],
                 (d[ns][2] + bv0) * cw1 * h1.x, (d[ns][3] + bv1) * cw1 * h1.y);
        }
    }
}

// ---------------- GIN branch kernels ----------------
__global__ void __launch_bounds__(256) segmax_kernel() {
    int idx = blockIdx.x * 256 + threadIdx.x;     // NT*HD
    int s = idx >> 7, f = idx & 127;
    int m = s >> 5, a = s & 31;
    int base = ((m << 8) + a) * HD + f;
    float v = g_x[base];
#pragma unroll
    for (int k = 1; k < 8; k++) v = fmaxf(v, g_x[base + k * 32 * HD]);
    g_xagg[idx] = v;
}

__global__ void __launch_bounds__(256) ginscatter_kernel(const int* __restrict__ eig,
                                                         const int* __restrict__ eag,
                                                         const float* __restrict__ bemb) {
    int idx = blockIdx.x * 256 + threadIdx.x;     // EGRAPH*HD
    int e = idx >> 7, f = idx & 127;
    int gr = eig[e], gc = eig[EGRAPH + e];
    float v = g_xagg[gr * HD + f] + bemb[eag[e] * HD + f];
    v = fmaxf(v, 0.f);
    atomicAdd(&g_magg[gc * HD + f], v);
}

__global__ void __launch_bounds__(256) ginpre_kernel(const float* __restrict__ geps, int l) {
    int idx = blockIdx.x * 256 + threadIdx.x;     // NT*HD
    float e = 1.f + geps[l];
    g_hg0[idx] = e * g_xagg[idx] + g_magg[idx];
}

// batchnorm over 8192 rows per column. SEL 0: g_hg1->g_hg2 ; SEL 1: g_hg3->g_hgf
template <int SEL>
__global__ void __launch_bounds__(256) bn_kernel(const float* __restrict__ gma,
                                                 const float* __restrict__ bta, int relu) {
    const float* X;
    float* Y;
    if constexpr (SEL == 0) { X = g_hg1; Y = g_hg2; }
    else                    { X = g_hg3; Y = g_hgf; }
    __shared__ float sred[256];
    int c = blockIdx.x, t = threadIdx.x;
    float v[32];
    float sum = 0.f;
#pragma unroll
    for (int i = 0; i < 32; i++) {
        v[i] = X[(t + (i << 8)) * HD + c];
        sum += v[i];
    }
    sred[t] = sum;
    __syncthreads();
    for (int off = 128; off; off >>= 1) {
        if (t < off) sred[t] += sred[t + off];
        __syncthreads();
    }
    float mu = sred[0] * (1.f / 8192.f);
    __syncthreads();
    float sq = 0.f;
#pragma unroll
    for (int i = 0; i < 32; i++) {
        float dd = v[i] - mu;
        sq = fmaf(dd, dd, sq);
    }
    sred[t] = sq;
    __syncthreads();
    for (int off = 128; off; off >>= 1) {
        if (t < off) sred[t] += sred[t + off];
        __syncthreads();
    }
    float var = sred[0] * (1.f / 8192.f);
    float sc = rsqrtf(var + 1e-5f) * gma[c];
    float sh = bta[c];
#pragma unroll
    for (int i = 0; i < 32; i++) {
        float o = (v[i] - mu) * sc + sh;
        if (relu) o = fmaxf(o, 0.f);
        Y[(t + (i << 8)) * HD + c] = o;
    }
}

// x = relu(x + t2 + hgf[cnb]) (cnb structural)
__global__ void __launch_bounds__(256) combine_kernel() {
    int idx = blockIdx.x * 256 + threadIdx.x;     // NN*HD
    int n = idx >> 7, f = idx & 127;
    int s = ((n >> 8) << 5) | (n & 31);
    float v = g_x[idx] + g_t2[idx] + g_hgf[s * HD + f];
    g_x[idx] = fmaxf(v, 0.f);
}

// ---------------- pooling (max over 256 contiguous nodes/molecule) ----------------
__global__ void __launch_bounds__(256) pool_kernel() {
    int idx = blockIdx.x * 256 + threadIdx.x;     // NMOL*HD
    int m = idx >> 7, f = idx & 127;
    const float* p = g_x + (m << 8) * HD + f;
    float v0 = -1e30f, v1 = -1e30f, v2 = -1e30f, v3 = -1e30f;
#pragma unroll 4
    for (int j = 0; j < 256; j += 4) {
        v0 = fmaxf(v0, p[(j + 0) * HD]);
        v1 = fmaxf(v1, p[(j + 1) * HD]);
        v2 = fmaxf(v2, p[(j + 2) * HD]);
        v3 = fmaxf(v3, p[(j + 3) * HD]);
    }
    g_pool[idx] = fmaxf(fmaxf(v0, v1), fmaxf(v2, v3));
}

// ---------------- output head ----------------
__global__ void __launch_bounds__(128) final_kernel(const float* __restrict__ w1,
                                                    const float* __restrict__ b1,
                                                    const float* __restrict__ w2,
                                                    const float* __restrict__ b2,
                                                    float* __restrict__ out) {
    __shared__ float sp[128];
    __shared__ float sr[128];
    int m = blockIdx.x, t = threadIdx.x;
    sp[t] = g_pool[m * HD + t];
    __syncthreads();
    float acc = b1[t];
#pragma unroll 8
    for (int k = 0; k < 128; k++) acc = fmaf(sp[k], w1[k * HD + t], acc);
    sr[t] = fmaxf(acc, 0.f) * w2[t];
    __syncthreads();
    for (int off = 64; off; off >>= 1) {
        if (t < off) sr[t] += sr[t + off];
        __syncthreads();
    }
    if (t == 0) out[m] = sr[0] + b2[0];
}

// ---------------- host launcher ----------------
extern "C" void kernel_launch(void* const* d_in, const int* in_sizes, int n_in,
                              void* d_out, int out_size) {
    const int*   x_topo = (const int*)d_in[0];
    const float* pos    = (const float*)d_in[1];
    const int*   eic    = (const int*)d_in[2];
    const int*   eig    = (const int*)d_in[3];
    const int*   eag    = (const int*)d_in[4];
    const float* aemb   = (const float*)d_in[8];
    const float* lin1w  = (const float*)d_in[9];
    const float* mw1    = (const float*)d_in[10];
    const float* mb1    = (const float*)d_in[11];
    const float* mw2    = (const float*)d_in[12];
    const float* mb2    = (const float*)d_in[13];
    const float* lin2w  = (const float*)d_in[14];
    const float* lin2b  = (const float*)d_in[15];
    const float* linw   = (const float*)d_in[16];
    const float* linb   = (const float*)d_in[17];
    const float* bemb   = (const float*)d_in[18];
    const float* gw1    = (const float*)d_in[19];
    const float* gb1    = (const float*)d_in[20];
    const float* gw2    = (const float*)d_in[21];
    const float* gb2    = (const float*)d_in[22];
    const float* gbng   = (const float*)d_in[23];
    const float* gbnb   = (const float*)d_in[24];
    const float* bng    = (const float*)d_in[25];
    const float* bnb    = (const float*)d_in[26];
    const float* geps   = (const float*)d_in[27];
    const float* ow1    = (const float*)d_in[28];
    const float* ob1    = (const float*)d_in[29];
    const float* ow2    = (const float*)d_in[30];
    const float* ob2    = (const float*)d_in[31];
    float* out = (float*)d_out;

    cudaFuncSetAttribute(edge_kernel, cudaFuncAttributeMaxDynamicSharedMemorySize,
                         EDGE_SMEM_BYTES);

    eprep_kernel<<<ECONF / 256, 256>>>(eic, pos);
    initx_kernel<<<NN * HD / 256, 256>>>(x_topo, aemb);

    for (int l = 0; l < 4; l++) {
        // CFConv branch
        gemm_kernel<64, 0><<<NN / 64, 256>>>(lin1w + l * 128 * 64, nullptr, 128, 0);
        zero_agg_kernel<<<NN * FD / 1024, 256>>>();
        edge_kernel<<<ECONF / 128, 256, EDGE_SMEM_BYTES>>>(
            mw1 + l * GD * 64, mb1 + l * 64, mw2 + l * 64 * 64, mb2 + l * 64, eic);
        gemm_kernel<128, 1><<<NN / 64, 256>>>(lin2w + l * 64 * 128, lin2b + l * 128, 64, 2);
        gemm_kernel<128, 2><<<NN / 64, 256>>>(linw + l * 128 * 128, linb + l * 128, 128, 1);
        // GIN branch
        segmax_kernel<<<NT * HD / 256, 256>>>();
        zero_magg_kernel<<<NT * HD / 1024, 256>>>();
        ginscatter_kernel<<<EGRAPH * HD / 256, 256>>>(eig, eag, bemb + l * 10 * HD);
        ginpre_kernel<<<NT * HD / 256, 256>>>(geps, l);
        gemm_kernel<128, 3><<<NT / 64, 256>>>(gw1 + l * 128 * 128, gb1 + l * 128, 128, 1);
        bn_kernel<0><<<128, 256>>>(gbng + l * 128, gbnb + l * 128, 1);
        gemm_kernel<128, 4><<<NT / 64, 256>>>(gw2 + l * 128 * 128, gb2 + l * 128, 128, 1);
        bn_kernel<1><<<128, 256>>>(bng + l * 128, bnb + l * 128, 0);
        // x = relu(x + t2 + hgf[cnb])
        combine_kernel<<<NN * HD / 256, 256>>>();
    }

    pool_kernel<<<NMOL * HD / 256, 256>>>();
    final_kernel<<<NMOL, 128>>>(ow1, ob1, ow2, ob2, out);
}